// round 8
// baseline (speedup 1.0000x reference)
#include <cuda_runtime.h>

#define FULL 0xffffffffu
typedef unsigned int u32;

constexpr int L = 16;
constexpr int CH = 8;                 // steps per chunk
constexpr int BUF_U32 = CH * 256;     // u32 per ring buffer (per warp, per stage)
constexpr float LOG2E = 1.4426950408889634f;
constexpr float LN2   = 0.6931471805599453f;

__device__ __forceinline__ float ex2f(float v) {
    float r; asm("ex2.approx.f32 %0,%1;" : "=f"(r) : "f"(v)); return r;
}
__device__ __forceinline__ u32 pkbf(float hi, float lo) {
    u32 r; asm("cvt.rn.bf16x2.f32 %0,%1,%2;" : "=r"(r) : "f"(hi), "f"(lo)); return r;
}
__device__ __forceinline__ u32 mulbf2(u32 a, u32 b) {
    u32 r; asm("mul.rn.bf16x2 %0,%1,%2;" : "=r"(r) : "r"(a), "r"(b)); return r;
}
__device__ __forceinline__ float bflo(u32 v) { return __uint_as_float(v << 16); }
__device__ __forceinline__ float bfhi(u32 v) { return __uint_as_float(v & 0xffff0000u); }

__device__ __forceinline__ void mma16816(
    float& d0, float& d1, float& d2, float& d3,
    u32 a0, u32 a1, u32 a2, u32 a3, u32 b0, u32 b1)
{
    asm volatile(
        "mma.sync.aligned.m16n8k16.row.col.f32.bf16.bf16.f32 "
        "{%0,%1,%2,%3}, {%4,%5,%6,%7}, {%8,%9}, {%10,%11,%12,%13};"
        : "=f"(d0), "=f"(d1), "=f"(d2), "=f"(d3)
        : "r"(a0), "r"(a1), "r"(a2), "r"(a3), "r"(b0), "r"(b1),
          "f"(0.f), "f"(0.f), "f"(0.f), "f"(0.f));
}

#define PAIR_BAR(id) asm volatile("bar.sync %0, 64;" :: "r"(id) : "memory")

// Block = 384 threads = 12 warps, 32 batches:
//  w0-3 : MMA consumers  (w0: fwd b0-15, w1: fwd b16-31, w2: bwd b0-15, w3: bwd b16-31)
//  w4-7 : exp producers paired with w0-3 (named barrier 1+rw, double-buffered ring)
//  w8-11: emit + transition scores
// Ring buffers live in 64KB dynamic shared memory.
__global__ __launch_bounds__(384, 1) void crf_kernel(
    const float* __restrict__ x, const float* __restrict__ trans,
    const int* __restrict__ label, const int* __restrict__ length,
    float* __restrict__ out, int B, int T)
{
    extern __shared__ u32 dynBuf[];   // [4 warps][2 stages][BUF_U32]
    __shared__ float sE[L * L];
    __shared__ float sT[L * L];
    __shared__ u32   sFA[2][32][4];
    __shared__ int   sMf[2][16];
    __shared__ float sScore[32];

    int tid  = threadIdx.x;
    int lane = tid & 31;
    int w    = tid >> 5;

    if (tid < L * L) {
        float tv = trans[tid];
        sT[tid] = tv;
        sE[tid] = tv * LOG2E;
    }
    __syncthreads();

    int blockBase = blockIdx.x * 32;

    if (w < 4) {
        // ================= consumer (MMA recursion) =================
        bool isBwd = w >= 2;
        int grp = w & 1;
        int g   = lane >> 2;
        int tig = lane & 3;
        int bBase = blockBase + grp * 16;
        int b_lo = bBase + g, b_hi = bBase + g + 8;
        int lenL = length[b_lo], lenH = length[b_hi];
        int mL = (lenL - 1) >> 1, mH = (lenH - 1) >> 1;
        int cntL = isBwd ? max(lenL - 2 - mL, 0) : mL;
        int cntH = isBwd ? max(lenH - 2 - mH, 0) : mH;

        int kMax = max(cntL, cntH);
#pragma unroll
        for (int o = 1; o <= 16; o <<= 1)
            kMax = max(kMax, __shfl_xor_sync(FULL, kMax, o));
        int nChunks = (kMax + CH - 1) / CH;

        // B fragments (constant): fwd B[k][n]=E[k][n]; bwd B[k][n]=E[n][k]
        u32 b00, b01, b10, b11;
        {
            int k0 = tig * 2;
            float e00, e01, e02, e03, e10, e11, e12, e13;
            if (!isBwd) {
                e00 = sE[k0 * L + g];       e01 = sE[(k0 + 1) * L + g];
                e02 = sE[(k0 + 8) * L + g]; e03 = sE[(k0 + 9) * L + g];
                e10 = sE[k0 * L + g + 8];       e11 = sE[(k0 + 1) * L + g + 8];
                e12 = sE[(k0 + 8) * L + g + 8]; e13 = sE[(k0 + 9) * L + g + 8];
            } else {
                e00 = sE[g * L + k0];       e01 = sE[g * L + k0 + 1];
                e02 = sE[g * L + k0 + 8];   e03 = sE[g * L + k0 + 9];
                e10 = sE[(g + 8) * L + k0];     e11 = sE[(g + 8) * L + k0 + 1];
                e12 = sE[(g + 8) * L + k0 + 8]; e13 = sE[(g + 8) * L + k0 + 9];
            }
            b00 = pkbf(ex2f(e01), ex2f(e00));
            b01 = pkbf(ex2f(e03), ex2f(e02));
            b10 = pkbf(ex2f(e11), ex2f(e10));
            b11 = pkbf(ex2f(e13), ex2f(e12));
        }

        // init state from gmem: exp of row 0 (fwd) / len-1 (bwd)
        const float* pL = x + (size_t)b_lo * T * L + tig * 2;
        const float* pH = x + (size_t)b_hi * T * L + tig * 2;
        int irL = isBwd ? (lenL - 1) : 0;
        int irH = isBwd ? (lenH - 1) : 0;
        float2 iLa = *(const float2*)(pL + (size_t)irL * L);
        float2 iLb = *(const float2*)(pL + (size_t)irL * L + 8);
        float2 iHa = *(const float2*)(pH + (size_t)irH * L);
        float2 iHb = *(const float2*)(pH + (size_t)irH * L + 8);
        u32 A0 = pkbf(ex2f(iLa.y * LOG2E), ex2f(iLa.x * LOG2E));
        u32 A1 = pkbf(ex2f(iHa.y * LOG2E), ex2f(iHa.x * LOG2E));
        u32 A2 = pkbf(ex2f(iLb.y * LOG2E), ex2f(iLb.x * LOG2E));
        u32 A3 = pkbf(ex2f(iHb.y * LOG2E), ex2f(iHb.x * LOG2E));
        int MsL = 0, MsH = 0;

        int barId = 1 + w;
        for (int ch = 0; ch < nChunks; ++ch) {
            PAIR_BAR(barId);
            const u32* src = dynBuf + (w * 2 + (ch & 1)) * BUF_U32;
#pragma unroll
            for (int kk = 0; kk < CH; ++kk) {
                int k = ch * CH + kk;
                u32 e0 = src[kk * 256 + lane];
                u32 e1 = src[kk * 256 + 64 + lane];
                u32 e2 = src[kk * 256 + 128 + lane];
                u32 e3 = src[kk * 256 + 192 + lane];

                float d0, d1, d2, d3, f0, f1, f2, f3;
                mma16816(d0, d1, d2, d3, A0, A1, A2, A3, b00, b01);
                mma16816(f0, f1, f2, f3, A0, A1, A2, A3, b10, b11);

                u32 n0 = mulbf2(pkbf(d1, d0), e0);
                u32 n1 = mulbf2(pkbf(d3, d2), e1);
                u32 n2 = mulbf2(pkbf(f1, f0), e2);
                u32 n3 = mulbf2(pkbf(f3, f2), e3);

                bool aL = k < cntL, aH = k < cntH;
                A0 = aL ? n0 : A0;  A2 = aL ? n2 : A2;
                A1 = aH ? n1 : A1;  A3 = aH ? n3 : A3;

                if (kk == CH - 1) {   // rescale once per chunk
                    u32 s0 = __shfl_sync(FULL, A0, lane & ~3);
                    u32 s1 = __shfl_sync(FULL, A1, lane & ~3);
                    int eeL = (int)((s0 >> 7) & 0xff) - 127;
                    int eeH = (int)((s1 >> 7) & 0xff) - 127;
                    u32 hL = (u32)(127 - eeL) << 7;
                    u32 hH = (u32)(127 - eeH) << 7;
                    u32 scL = aL ? (hL | (hL << 16)) : 0x3f803f80u;
                    u32 scH = aH ? (hH | (hH << 16)) : 0x3f803f80u;
                    MsL += aL ? eeL : 0;
                    MsH += aH ? eeH : 0;
                    A0 = mulbf2(A0, scL); A2 = mulbf2(A2, scL);
                    A1 = mulbf2(A1, scH); A3 = mulbf2(A3, scH);
                }
            }
        }

        if (!isBwd) {
            sFA[grp][lane][0] = A0; sFA[grp][lane][1] = A1;
            sFA[grp][lane][2] = A2; sFA[grp][lane][3] = A3;
            if (tig == 0) { sMf[grp][g] = MsL; sMf[grp][g + 8] = MsH; }
            __syncthreads();
        } else {
            float d0, d1, d2, d3, f0, f1, f2, f3;
            mma16816(d0, d1, d2, d3, A0, A1, A2, A3, b00, b01);
            mma16816(f0, f1, f2, f3, A0, A1, A2, A3, b10, b11);
            if (lenL == 1) { d0 = d1 = 1.f; f0 = f1 = 1.f; }
            if (lenH == 1) { d2 = d3 = 1.f; f2 = f3 = 1.f; }

            __syncthreads();

            u32 a0 = sFA[grp][lane][0], a1 = sFA[grp][lane][1];
            u32 a2 = sFA[grp][lane][2], a3 = sFA[grp][lane][3];
            float pLo = d0 * bflo(a0) + d1 * bfhi(a0) + f0 * bflo(a2) + f1 * bfhi(a2);
            float pHi = d2 * bflo(a1) + d3 * bfhi(a1) + f2 * bflo(a3) + f3 * bfhi(a3);
            pLo += __shfl_xor_sync(FULL, pLo, 1);
            pLo += __shfl_xor_sync(FULL, pLo, 2);
            pHi += __shfl_xor_sync(FULL, pHi, 1);
            pHi += __shfl_xor_sync(FULL, pHi, 2);
            float zL = __logf(pLo) + (float)(MsL + sMf[grp][g]) * LN2;
            float zH = __logf(pHi) + (float)(MsH + sMf[grp][g + 8]) * LN2;
            if (tig == 0) {
                out[b_lo] = zL - sScore[grp * 16 + g];
                out[b_hi] = zH - sScore[grp * 16 + g + 8];
            }
        }
    } else if (w < 8) {
        // ================= producer (load + exp) =================
        int rw = w - 4;
        bool isBwd = rw >= 2;
        int grp = rw & 1;
        int bp = lane >> 1;        // batch 0..15
        int hp = lane & 1;         // state half
        int b  = blockBase + grp * 16 + bp;

        const float* xB = x + (size_t)b * T * L + hp * 8;
        int len = length[b];
        int m = (len - 1) >> 1;
        int cnt  = isBwd ? max(len - 2 - m, 0) : m;
        int base = isBwd ? (len - 2) : 1;
        int dir  = isBwd ? -1 : 1;
        int cl   = max(cnt - 1, 0);

        int kMax = cnt;
#pragma unroll
        for (int o = 1; o <= 16; o <<= 1)
            kMax = max(kMax, __shfl_xor_sync(FULL, kMax, o));
        int nChunks = (kMax + CH - 1) / CH;

        int q = hp * 2 + (bp >> 3);
        u32* dstBase = dynBuf + rw * 2 * BUF_U32 + q * 64 + (bp & 7) * 4;
        int barId = 1 + rw;

        float4 va[CH], vb[CH];
        if (nChunks > 0) {
#pragma unroll
            for (int kk = 0; kk < CH; ++kk) {
                int row = max(base + dir * min(kk, cl), 0);
                const float4* pr = (const float4*)(xB + (size_t)row * L);
                va[kk] = pr[0]; vb[kk] = pr[1];
            }
        }
        for (int ch = 0; ch < nChunks; ++ch) {
            u32* dst = dstBase + (ch & 1) * BUF_U32;
#pragma unroll
            for (int kk = 0; kk < CH; ++kk) {
                u32 p0 = pkbf(ex2f(va[kk].y * LOG2E), ex2f(va[kk].x * LOG2E));
                u32 p1 = pkbf(ex2f(va[kk].w * LOG2E), ex2f(va[kk].z * LOG2E));
                u32 p2 = pkbf(ex2f(vb[kk].y * LOG2E), ex2f(vb[kk].x * LOG2E));
                u32 p3 = pkbf(ex2f(vb[kk].w * LOG2E), ex2f(vb[kk].z * LOG2E));
                *(uint4*)(dst + kk * 256) = make_uint4(p0, p1, p2, p3);
            }
            if (ch + 1 < nChunks) {     // prefetch next chunk before the bar
#pragma unroll
                for (int kk = 0; kk < CH; ++kk) {
                    int k = (ch + 1) * CH + kk;
                    int row = max(base + dir * min(k, cl), 0);
                    const float4* pr = (const float4*)(xB + (size_t)row * L);
                    va[kk] = pr[0]; vb[kk] = pr[1];
                }
            }
            PAIR_BAR(barId);
        }
        __syncthreads();
    } else {
        // ================= emit / transition warps =================
        int we = w - 8;
#pragma unroll 1
        for (int k2 = 0; k2 < 8; ++k2) {
            int sl = we * 8 + k2;
            int bb = blockBase + sl;
            const int*   lb = label + (size_t)bb * T;
            const float* xb = x + (size_t)bb * T * L;
            int ll = length[bb];

            float acc = 0.f;
            for (int t = lane; t < ll; t += 32) {
                int lab = lb[t];
                acc += __ldg(xb + t * L + lab);
                if (t >= 1) acc += sT[lb[t - 1] * L + lab];
            }
            acc += __shfl_xor_sync(FULL, acc, 16);
            acc += __shfl_xor_sync(FULL, acc, 8);
            acc += __shfl_xor_sync(FULL, acc, 4);
            acc += __shfl_xor_sync(FULL, acc, 2);
            acc += __shfl_xor_sync(FULL, acc, 1);
            if (lane == 0) sScore[sl] = acc;
        }
        __syncthreads();
    }
}

extern "C" void kernel_launch(void* const* d_in, const int* in_sizes, int n_in,
                              void* d_out, int out_size) {
    const float* x      = (const float*)d_in[0];
    const float* trans  = (const float*)d_in[1];
    const int*   label  = (const int*)d_in[2];
    const int*   length = (const int*)d_in[3];
    float*       out    = (float*)d_out;

    int B = in_sizes[3];                 // 4096
    int T = in_sizes[2] / B;             // 512

    size_t dynSmem = (size_t)4 * 2 * BUF_U32 * sizeof(u32);   // 64KB ring
    static int attrSet = 0;
    if (!attrSet) {
        cudaFuncSetAttribute(crf_kernel,
                             cudaFuncAttributeMaxDynamicSharedMemorySize,
                             (int)dynSmem);
        attrSet = 1;
    }

    int grid = (B + 31) / 32;            // 32 batches per block, 128 blocks
    crf_kernel<<<grid, 384, dynSmem>>>(x, trans, label, length, out, B, T);
}

// round 9
// speedup vs baseline: 1.1416x; 1.1416x over previous
#include <cuda_runtime.h>

#define FULL 0xffffffffu
typedef unsigned int u32;

constexpr int L = 16;
constexpr float LOG2E = 1.4426950408889634f;
constexpr float LN2   = 0.6931471805599453f;

__device__ __forceinline__ float ex2f(float v) {
    float r; asm("ex2.approx.f32 %0,%1;" : "=f"(r) : "f"(v)); return r;
}
__device__ __forceinline__ u32 pkbf(float hi, float lo) {
    u32 r; asm("cvt.rn.bf16x2.f32 %0,%1,%2;" : "=r"(r) : "f"(hi), "f"(lo)); return r;
}
__device__ __forceinline__ u32 mulbf2(u32 a, u32 b) {
    u32 r; asm("mul.rn.bf16x2 %0,%1,%2;" : "=r"(r) : "r"(a), "r"(b)); return r;
}
__device__ __forceinline__ float bflo(u32 v) { return __uint_as_float(v << 16); }
__device__ __forceinline__ float bfhi(u32 v) { return __uint_as_float(v & 0xffff0000u); }

__device__ __forceinline__ void mma16816(
    float& d0, float& d1, float& d2, float& d3,
    u32 a0, u32 a1, u32 a2, u32 a3, u32 b0, u32 b1)
{
    asm volatile(
        "mma.sync.aligned.m16n8k16.row.col.f32.bf16.bf16.f32 "
        "{%0,%1,%2,%3}, {%4,%5,%6,%7}, {%8,%9}, {%10,%11,%12,%13};"
        : "=f"(d0), "=f"(d1), "=f"(d2), "=f"(d3)
        : "r"(a0), "r"(a1), "r"(a2), "r"(a3), "r"(b0), "r"(b1),
          "f"(0.f), "f"(0.f), "f"(0.f), "f"(0.f));
}

// Block = 256 threads = 8 warps, 32 batches:
//  warp 0: fwd batches 0-15, warp 1: fwd 16-31, warp 2: bwd 0-15, warp 3: bwd 16-31
//  warps 4-7: emit + transition scores (8 batches each)
// State s = A-fragment (bf16) of m16n8k16. One step: 2 MMAs -> D(fp32) ->
// bf16 pack -> HMUL2 by pre-packed exp(x_t) -> next A. exp pipeline runs one
// step ahead so MUFU latency is off the serial chain.
__global__ __launch_bounds__(256, 1) void crf_kernel(
    const float* __restrict__ x, const float* __restrict__ trans,
    const int* __restrict__ label, const int* __restrict__ length,
    float* __restrict__ out, int B, int T)
{
    __shared__ float sE[L * L];
    __shared__ float sT[L * L];
    __shared__ u32   sFA[2][32][4];
    __shared__ int   sMf[2][16];
    __shared__ float sScore[32];

    int tid  = threadIdx.x;
    int lane = tid & 31;
    int w    = tid >> 5;
    int g    = lane >> 2;
    int tig  = lane & 3;

    if (tid < L * L) {
        float tv = trans[tid];
        sT[tid] = tv;
        sE[tid] = tv * LOG2E;
    }
    __syncthreads();

    int blockBase = blockIdx.x * 32;

    if (w < 4) {
        bool isBwd = w >= 2;
        int grp = w & 1;
        int bBase = blockBase + grp * 16;
        int b_lo = bBase + g, b_hi = bBase + g + 8;
        int lenL = length[b_lo], lenH = length[b_hi];
        int mL = (lenL - 1) >> 1, mH = (lenH - 1) >> 1;
        int cntL = isBwd ? max(lenL - 2 - mL, 0) : mL;
        int cntH = isBwd ? max(lenH - 2 - mH, 0) : mH;
        int baseL = isBwd ? (lenL - 2) : 1;
        int baseH = isBwd ? (lenH - 2) : 1;
        int dir   = isBwd ? -1 : 1;
        int clL = max(cntL - 1, 0), clH = max(cntH - 1, 0);

        int kMax = max(cntL, cntH);
#pragma unroll
        for (int o = 1; o <= 16; o <<= 1)
            kMax = max(kMax, __shfl_xor_sync(FULL, kMax, o));
        int kMaxPad = (kMax + 3) & ~3;

        // B fragments (constant): fwd B[k][n]=E[k][n]; bwd B[k][n]=E[n][k]
        u32 b00, b01, b10, b11;
        {
            int k0 = tig * 2;
            float e00, e01, e02, e03, e10, e11, e12, e13;
            if (!isBwd) {
                e00 = sE[k0 * L + g];       e01 = sE[(k0 + 1) * L + g];
                e02 = sE[(k0 + 8) * L + g]; e03 = sE[(k0 + 9) * L + g];
                e10 = sE[k0 * L + g + 8];       e11 = sE[(k0 + 1) * L + g + 8];
                e12 = sE[(k0 + 8) * L + g + 8]; e13 = sE[(k0 + 9) * L + g + 8];
            } else {
                e00 = sE[g * L + k0];       e01 = sE[g * L + k0 + 1];
                e02 = sE[g * L + k0 + 8];   e03 = sE[g * L + k0 + 9];
                e10 = sE[(g + 8) * L + k0];     e11 = sE[(g + 8) * L + k0 + 1];
                e12 = sE[(g + 8) * L + k0 + 8]; e13 = sE[(g + 8) * L + k0 + 9];
            }
            b00 = pkbf(ex2f(e01), ex2f(e00));
            b01 = pkbf(ex2f(e03), ex2f(e02));
            b10 = pkbf(ex2f(e11), ex2f(e10));
            b11 = pkbf(ex2f(e13), ex2f(e12));
        }

        const float* pL = x + (size_t)b_lo * T * L + tig * 2;
        const float* pH = x + (size_t)b_hi * T * L + tig * 2;

        // init: s = exp(x at row 0 (fwd) / len-1 (bwd))
        int irL = isBwd ? (lenL - 1) : 0;
        int irH = isBwd ? (lenH - 1) : 0;
        float2 iLa = *(const float2*)(pL + (size_t)irL * L);
        float2 iLb = *(const float2*)(pL + (size_t)irL * L + 8);
        float2 iHa = *(const float2*)(pH + (size_t)irH * L);
        float2 iHb = *(const float2*)(pH + (size_t)irH * L + 8);
        u32 A0 = pkbf(ex2f(iLa.y * LOG2E), ex2f(iLa.x * LOG2E));
        u32 A1 = pkbf(ex2f(iHa.y * LOG2E), ex2f(iHa.x * LOG2E));
        u32 A2 = pkbf(ex2f(iLb.y * LOG2E), ex2f(iLb.x * LOG2E));
        u32 A3 = pkbf(ex2f(iHb.y * LOG2E), ex2f(iHb.x * LOG2E));
        int MsL = 0, MsH = 0;

        // 4-deep prefetch ring of x rows (clamped)
        float2 rLa[4], rLb[4], rHa[4], rHb[4];
#pragma unroll
        for (int d = 0; d < 4; ++d) {
            int rowL = max(baseL + dir * min(d, clL), 0);
            int rowH = max(baseH + dir * min(d, clH), 0);
            rLa[d] = *(const float2*)(pL + (size_t)rowL * L);
            rLb[d] = *(const float2*)(pL + (size_t)rowL * L + 8);
            rHa[d] = *(const float2*)(pH + (size_t)rowH * L);
            rHb[d] = *(const float2*)(pH + (size_t)rowH * L + 8);
        }

        // pre-packed exp for the CURRENT step (pipeline register)
        u32 eP0 = pkbf(ex2f(rLa[0].y * LOG2E), ex2f(rLa[0].x * LOG2E));
        u32 eP1 = pkbf(ex2f(rHa[0].y * LOG2E), ex2f(rHa[0].x * LOG2E));
        u32 eP2 = pkbf(ex2f(rLb[0].y * LOG2E), ex2f(rLb[0].x * LOG2E));
        u32 eP3 = pkbf(ex2f(rHb[0].y * LOG2E), ex2f(rHb[0].x * LOG2E));

        for (int k0 = 0; k0 < kMaxPad; k0 += 4) {
#pragma unroll
            for (int kk = 0; kk < 4; ++kk) {
                int k = k0 + kk;

                // issue prefetch of row k+4 early (lands in ring slot kk)
                int rowL = max(baseL + dir * min(k + 4, clL), 0);
                int rowH = max(baseH + dir * min(k + 4, clH), 0);
                float2 nLa = *(const float2*)(pL + (size_t)rowL * L);
                float2 nLb = *(const float2*)(pL + (size_t)rowL * L + 8);
                float2 nHa = *(const float2*)(pH + (size_t)rowH * L);
                float2 nHb = *(const float2*)(pH + (size_t)rowH * L + 8);

                float d0, d1, d2, d3, f0, f1, f2, f3;
                mma16816(d0, d1, d2, d3, A0, A1, A2, A3, b00, b01);
                mma16816(f0, f1, f2, f3, A0, A1, A2, A3, b10, b11);

                // exp pipeline: e for step k+1 from ring slot (kk+1)&3
                float2 xLa = rLa[(kk + 1) & 3], xLb = rLb[(kk + 1) & 3];
                float2 xHa = rHa[(kk + 1) & 3], xHb = rHb[(kk + 1) & 3];
                u32 nE0 = pkbf(ex2f(xLa.y * LOG2E), ex2f(xLa.x * LOG2E));
                u32 nE1 = pkbf(ex2f(xHa.y * LOG2E), ex2f(xHa.x * LOG2E));
                u32 nE2 = pkbf(ex2f(xLb.y * LOG2E), ex2f(xLb.x * LOG2E));
                u32 nE3 = pkbf(ex2f(xHb.y * LOG2E), ex2f(xHb.x * LOG2E));
                rLa[kk] = nLa; rLb[kk] = nLb; rHa[kk] = nHa; rHb[kk] = nHb;

                u32 n0 = mulbf2(pkbf(d1, d0), eP0);
                u32 n1 = mulbf2(pkbf(d3, d2), eP1);
                u32 n2 = mulbf2(pkbf(f1, f0), eP2);
                u32 n3 = mulbf2(pkbf(f3, f2), eP3);

                bool aL = k < cntL, aH = k < cntH;
                A0 = aL ? n0 : A0;  A2 = aL ? n2 : A2;
                A1 = aH ? n1 : A1;  A3 = aH ? n3 : A3;
                eP0 = nE0; eP1 = nE1; eP2 = nE2; eP3 = nE3;

                if ((k & 7) == 7) {   // exponent-only rescale per batch row
                    u32 s0 = __shfl_sync(FULL, A0, lane & ~3);
                    u32 s1 = __shfl_sync(FULL, A1, lane & ~3);
                    int eeL = (int)((s0 >> 7) & 0xff) - 127;
                    int eeH = (int)((s1 >> 7) & 0xff) - 127;
                    u32 hL = (u32)(127 - eeL) << 7;
                    u32 hH = (u32)(127 - eeH) << 7;
                    u32 scL = aL ? (hL | (hL << 16)) : 0x3f803f80u;
                    u32 scH = aH ? (hH | (hH << 16)) : 0x3f803f80u;
                    MsL += aL ? eeL : 0;
                    MsH += aH ? eeH : 0;
                    A0 = mulbf2(A0, scL); A2 = mulbf2(A2, scL);
                    A1 = mulbf2(A1, scH); A3 = mulbf2(A3, scH);
                }
            }
        }

        if (!isBwd) {
            sFA[grp][lane][0] = A0; sFA[grp][lane][1] = A1;
            sFA[grp][lane][2] = A2; sFA[grp][lane][3] = A3;
            if (tig == 0) { sMf[grp][g] = MsL; sMf[grp][g + 8] = MsH; }
            __syncthreads();
        } else {
            // beta_m = E * q~ : one more (plain) double-MMA
            float d0, d1, d2, d3, f0, f1, f2, f3;
            mma16816(d0, d1, d2, d3, A0, A1, A2, A3, b00, b01);
            mma16816(f0, f1, f2, f3, A0, A1, A2, A3, b10, b11);
            if (lenL == 1) { d0 = d1 = 1.f; f0 = f1 = 1.f; }
            if (lenH == 1) { d2 = d3 = 1.f; f2 = f3 = 1.f; }

            __syncthreads();

            u32 a0 = sFA[grp][lane][0], a1 = sFA[grp][lane][1];
            u32 a2 = sFA[grp][lane][2], a3 = sFA[grp][lane][3];
            float pLo = d0 * bflo(a0) + d1 * bfhi(a0) + f0 * bflo(a2) + f1 * bfhi(a2);
            float pHi = d2 * bflo(a1) + d3 * bfhi(a1) + f2 * bflo(a3) + f3 * bfhi(a3);
            pLo += __shfl_xor_sync(FULL, pLo, 1);
            pLo += __shfl_xor_sync(FULL, pLo, 2);
            pHi += __shfl_xor_sync(FULL, pHi, 1);
            pHi += __shfl_xor_sync(FULL, pHi, 2);
            float zL = __logf(pLo) + (float)(MsL + sMf[grp][g]) * LN2;
            float zH = __logf(pHi) + (float)(MsH + sMf[grp][g + 8]) * LN2;
            if (tig == 0) {
                out[b_lo] = zL - sScore[grp * 16 + g];
                out[b_hi] = zH - sScore[grp * 16 + g + 8];
            }
        }
    } else {
        // ---------------- emit / transition warps ----------------
        int we = w - 4;
#pragma unroll 1
        for (int k2 = 0; k2 < 8; ++k2) {
            int sl = we * 8 + k2;
            int bb = blockBase + sl;
            const int*   lb = label + (size_t)bb * T;
            const float* xb = x + (size_t)bb * T * L;
            int ll = length[bb];

            float acc = 0.f;
            for (int t = lane; t < ll; t += 32) {
                int lab = lb[t];
                acc += __ldg(xb + t * L + lab);
                if (t >= 1) acc += sT[lb[t - 1] * L + lab];
            }
            acc += __shfl_xor_sync(FULL, acc, 16);
            acc += __shfl_xor_sync(FULL, acc, 8);
            acc += __shfl_xor_sync(FULL, acc, 4);
            acc += __shfl_xor_sync(FULL, acc, 2);
            acc += __shfl_xor_sync(FULL, acc, 1);
            if (lane == 0) sScore[sl] = acc;
        }
        __syncthreads();
    }
}

extern "C" void kernel_launch(void* const* d_in, const int* in_sizes, int n_in,
                              void* d_out, int out_size) {
    const float* x      = (const float*)d_in[0];
    const float* trans  = (const float*)d_in[1];
    const int*   label  = (const int*)d_in[2];
    const int*   length = (const int*)d_in[3];
    float*       out    = (float*)d_out;

    int B = in_sizes[3];                 // 4096
    int T = in_sizes[2] / B;             // 512

    int grid = (B + 31) / 32;            // 32 batches per block, 128 blocks
    crf_kernel<<<grid, 256>>>(x, trans, label, length, out, B, T);
}